// round 10
// baseline (speedup 1.0000x reference)
#include <cuda_runtime.h>
#include <cstdint>
#include <cmath>
#include <vector>
#include <algorithm>
#include <utility>

// Problem constants
constexpr int NS  = 8;     // samples
constexpr int NA  = 1024;  // assets
constexpr int NK  = 5;     // clusters
constexpr int NIT = 30;    // max kmeans iterations
constexpr int NCH = 16;    // row-chunks for centroid partial sums (64 rows each)

// ---------------- device scratch (static: no runtime allocation) ----------------
__device__ float g_corr[NS][NA][NA];      // 32 MB
__device__ float g_rstd[NS][NA];
__device__ float g_xn[NS][NA];
__device__ float g_cent[NS][NK][NA];
__device__ float g_cn[NS][NK];
__device__ int   g_ixs[NS][NA];
__device__ float g_mind[NS][NA];
__device__ float g_prev[NS];
__device__ int   g_flag[NS];
__device__ int   g_cnt[NS][NK];
__device__ float g_part[NS][NCH][NK][NA]; // centroid partial sums
__device__ int   g_clidx[NS][NA];
__device__ int   g_cloff[NS][NK];
__device__ int   g_suboff[NS][NK];
__device__ float g_sub[NS][NA * NA];      // 32 MB, packed per-cluster submatrices
__device__ float g_wintra[NS][NK][NA];
__device__ float g_Y[NS][NA][NK];
__device__ float g_inter[NS][NK][NK];
__device__ float g_winter[NS][NK];

struct InitIdx { int v[NS * NK]; };

// ---------------- kernels ----------------

__global__ void __launch_bounds__(NA) k_prep(const float* __restrict__ cov) {
    int s = blockIdx.x, i = threadIdx.x;
    float d = cov[((size_t)s * NA + i) * NA + i];
    g_rstd[s][i] = rsqrtf(d);
    if (i == 0) { g_flag[s] = 0; g_prev[s] = __int_as_float(0x7f800000); }
}

// corr[s][i][j] = cov/(std_i std_j); also row norms xn (fixed-order tree reduce)
__global__ void __launch_bounds__(256) k_corr(const float* __restrict__ cov) {
    int b = blockIdx.x, s = b >> 10, i = b & (NA - 1);
    const float* row = cov + ((size_t)s * NA + i) * NA;
    float ri = g_rstd[s][i];
    __shared__ float sm[256];
    float acc = 0.f;
    for (int j = threadIdx.x; j < NA; j += 256) {
        float v = row[j] * ri * g_rstd[s][j];
        g_corr[s][i][j] = v;
        acc += v * v;
    }
    sm[threadIdx.x] = acc; __syncthreads();
    for (int st = 128; st > 0; st >>= 1) {
        if (threadIdx.x < st) sm[threadIdx.x] += sm[threadIdx.x + st];
        __syncthreads();
    }
    if (threadIdx.x == 0) g_xn[s][i] = sm[0];
}

__global__ void __launch_bounds__(NA) k_initc(InitIdx ii) {
    int s = blockIdx.x, d = threadIdx.x;
    __shared__ float sm[NA];
    float cv[NK];
#pragma unroll
    for (int c = 0; c < NK; c++) {
        int idx = ii.v[s * NK + c];
        cv[c] = g_corr[s][idx][d];
        g_cent[s][c][d] = cv[c];
    }
    for (int c = 0; c < NK; c++) {
        sm[d] = cv[c] * cv[c]; __syncthreads();
        for (int st = 512; st > 0; st >>= 1) {
            if (d < st) sm[d] += sm[d + st];
            __syncthreads();
        }
        if (d == 0) g_cn[s][c] = sm[0];
        __syncthreads();
    }
}

// distances + argmin; one block = 16 rows (8 warps x 2 rows), centers in smem
__global__ void __launch_bounds__(256) k_assign() {
    int s = blockIdx.y;
    if (g_flag[s]) return;
    __shared__ float sc[NK * NA];
    __shared__ float scn[NK];
    for (int t = threadIdx.x; t < NK * NA; t += 256)
        sc[t] = ((const float*)g_cent[s])[t];
    if (threadIdx.x < NK) scn[threadIdx.x] = g_cn[s][threadIdx.x];
    __syncthreads();
    int warp = threadIdx.x >> 5, lane = threadIdx.x & 31;
    for (int rr = 0; rr < 2; rr++) {
        int row = blockIdx.x * 16 + warp * 2 + rr;
        const float* xr = g_corr[s][row];
        float a0 = 0, a1 = 0, a2 = 0, a3 = 0, a4 = 0;
        for (int dd = lane; dd < NA; dd += 32) {
            float x = xr[dd];
            a0 += x * sc[0 * NA + dd]; a1 += x * sc[1 * NA + dd];
            a2 += x * sc[2 * NA + dd]; a3 += x * sc[3 * NA + dd];
            a4 += x * sc[4 * NA + dd];
        }
        for (int off = 16; off > 0; off >>= 1) {
            a0 += __shfl_down_sync(0xffffffffu, a0, off);
            a1 += __shfl_down_sync(0xffffffffu, a1, off);
            a2 += __shfl_down_sync(0xffffffffu, a2, off);
            a3 += __shfl_down_sync(0xffffffffu, a3, off);
            a4 += __shfl_down_sync(0xffffffffu, a4, off);
        }
        if (lane == 0) {
            float xn = g_xn[s][row];
            float d0 = fmaxf(xn + scn[0] - 2.f * a0, 0.f);
            float d1 = fmaxf(xn + scn[1] - 2.f * a1, 0.f);
            float d2 = fmaxf(xn + scn[2] - 2.f * a2, 0.f);
            float d3 = fmaxf(xn + scn[3] - 2.f * a3, 0.f);
            float d4 = fmaxf(xn + scn[4] - 2.f * a4, 0.f);
            float best = d0; int bi = 0;
            if (d1 < best) { best = d1; bi = 1; }
            if (d2 < best) { best = d2; bi = 2; }
            if (d3 < best) { best = d3; bi = 3; }
            if (d4 < best) { best = d4; bi = 4; }
            g_ixs[s][row] = bi;
            g_mind[s][row] = best;
        }
    }
}

// potential (fixed-order tree), counts (int atomics: deterministic), convergence
__global__ void __launch_bounds__(NA) k_reduce(int iter) {
    int s = blockIdx.x, t = threadIdx.x;
    if (g_flag[s]) return;
    __shared__ float sm[NA];
    __shared__ int scnt[NK];
    if (t < NK) scnt[t] = 0;
    __syncthreads();
    atomicAdd(&scnt[g_ixs[s][t]], 1);
    sm[t] = g_mind[s][t];
    __syncthreads();
    for (int st = 512; st > 0; st >>= 1) {
        if (t < st) sm[t] += sm[t + st];
        __syncthreads();
    }
    if (t < NK) g_cnt[s][t] = scnt[t];
    if (t == 0) {
        float pot = sm[0];
        if (iter > 0 && fabsf(pot - g_prev[s]) < 1e-5f) g_flag[s] = 1;
        g_prev[s] = pot;
    }
}

// centroid partial sums over a 64-row chunk
__global__ void __launch_bounds__(256) k_updA() {
    int s = blockIdx.y;
    if (g_flag[s]) return;
    int chunk = blockIdx.x, t = threadIdx.x;
    __shared__ int sixs[64];
    if (t < 64) sixs[t] = g_ixs[s][chunk * 64 + t];
    __syncthreads();
    float acc[NK][4];
#pragma unroll
    for (int c = 0; c < NK; c++)
#pragma unroll
        for (int j = 0; j < 4; j++) acc[c][j] = 0.f;
    for (int ii = 0; ii < 64; ii++) {
        int row = chunk * 64 + ii;
        int ix = sixs[ii];
        const float* xr = g_corr[s][row];
        float m[NK];
#pragma unroll
        for (int c = 0; c < NK; c++) m[c] = (ix == c) ? 1.f : 0.f;
#pragma unroll
        for (int j = 0; j < 4; j++) {
            float x = xr[t + 256 * j];
#pragma unroll
            for (int c = 0; c < NK; c++) acc[c][j] += m[c] * x;
        }
    }
#pragma unroll
    for (int c = 0; c < NK; c++)
#pragma unroll
        for (int j = 0; j < 4; j++)
            g_part[s][chunk][c][t + 256 * j] = acc[c][j];
}

// combine partials -> new centers; center norms via fixed-order reductions
__global__ void __launch_bounds__(NA) k_updB() {
    int s = blockIdx.x;
    if (g_flag[s]) return;
    int d = threadIdx.x;
    __shared__ float sm[NA];
    float nc[NK];
#pragma unroll
    for (int c = 0; c < NK; c++) {
        float sum = 0.f;
        for (int ch = 0; ch < NCH; ch++) sum += g_part[s][ch][c][d];
        int cnt = g_cnt[s][c];
        float v = (cnt > 0) ? sum / (float)cnt : g_cent[s][c][d];
        nc[c] = v;
        g_cent[s][c][d] = v;
    }
    for (int c = 0; c < NK; c++) {
        sm[d] = nc[c] * nc[c]; __syncthreads();
        for (int st = 512; st > 0; st >>= 1) {
            if (d < st) sm[d] += sm[d + st];
            __syncthreads();
        }
        if (d == 0) g_cn[s][c] = sm[0];
        __syncthreads();
    }
}

// cluster member lists + packed submatrix offsets (serial per-sample, trivial)
__global__ void __launch_bounds__(32) k_lists() {
    int s = blockIdx.x;
    if (threadIdx.x != 0) return;
    int off = 0, soff = 0;
    int pos[NK];
    for (int k = 0; k < NK; k++) {
        g_cloff[s][k] = off;
        g_suboff[s][k] = soff;
        pos[k] = off;
        int n = g_cnt[s][k];
        off += n; soff += n * n;
    }
    for (int i = 0; i < NA; i++) {
        int k = g_ixs[s][i];
        g_clidx[s][pos[k]++] = i;
    }
}

// gather per-cluster sub-covariance (NOTE: covariance, not correlation)
__global__ void __launch_bounds__(256) k_gather(const float* __restrict__ cov) {
    int s = blockIdx.z, k = blockIdx.y;
    int n = g_cnt[s][k];
    if (n == 0) return;
    __shared__ int sidx[NA];
    int off = g_cloff[s][k];
    for (int t = threadIdx.x; t < n; t += 256) sidx[t] = g_clidx[s][off + t];
    __syncthreads();
    float* sub = &g_sub[s][g_suboff[s][k]];
    for (int r = blockIdx.x; r < n; r += gridDim.x) {
        const float* crow = cov + ((size_t)s * NA + sidx[r]) * NA;
        for (int c = threadIdx.x; c < n; c += 256)
            sub[r * n + c] = crow[sidx[c]];
    }
}

// Cholesky (right-looking, symmetric full update) + solve L L^T w = 1; scatter w/denom
__global__ void __launch_bounds__(256) k_chol() {
    int s = blockIdx.y, k = blockIdx.x, t = threadIdx.x;
    for (int i = t; i < NA; i += 256) g_wintra[s][k][i] = 0.f;
    int n = g_cnt[s][k];
    if (n == 0) return;
    float* M = &g_sub[s][g_suboff[s][k]];
    __shared__ float s_col[NA];
    __shared__ float s_vec[NA];
    __shared__ float s_red[256];
    __shared__ float s_d;
    for (int j = 0; j < n; j++) {
        __syncthreads();
        if (t == 0) s_d = sqrtf(M[j * n + j]);
        __syncthreads();
        float dd = s_d;
        for (int r = j + 1 + t; r < n; r += 256) {
            float v = M[r * n + j] / dd;
            M[r * n + j] = v;
            s_col[r] = v;
        }
        if (t == 0) M[j * n + j] = dd;
        __syncthreads();
        int m = n - j - 1;
        int mm = m * m;
        for (int e = t; e < mm; e += 256) {
            int r = j + 1 + e / m, c = j + 1 + e % m;
            M[r * n + c] -= s_col[r] * s_col[c];
        }
    }
    __syncthreads();
    for (int i = t; i < n; i += 256) s_vec[i] = 1.f;
    __syncthreads();
    // forward: L y = 1
    for (int j = 0; j < n; j++) {
        if (t == 0) s_vec[j] = s_vec[j] / M[j * n + j];
        __syncthreads();
        float yj = s_vec[j];
        for (int r = j + 1 + t; r < n; r += 256) s_vec[r] -= M[r * n + j] * yj;
        __syncthreads();
    }
    // backward: L^T w = y
    for (int j = n - 1; j >= 0; j--) {
        if (t == 0) s_vec[j] = s_vec[j] / M[j * n + j];
        __syncthreads();
        float wj = s_vec[j];
        for (int r = t; r < j; r += 256) s_vec[r] -= M[j * n + r] * wj;
        __syncthreads();
    }
    float acc = 0.f;
    for (int i = t; i < n; i += 256) acc += s_vec[i];
    s_red[t] = acc; __syncthreads();
    for (int st = 128; st > 0; st >>= 1) {
        if (t < st) s_red[t] += s_red[t + st];
        __syncthreads();
    }
    float denom = s_red[0];
    int off = g_cloff[s][k];
    for (int i = t; i < n; i += 256)
        g_wintra[s][k][g_clidx[s][off + i]] = s_vec[i] / denom;
}

// Y[s][a][l] = sum_b cov[a][b] * wintra[l][b]
__global__ void __launch_bounds__(256) k_Y(const float* __restrict__ cov) {
    int b = blockIdx.x, s = b >> 10, a = b & (NA - 1);
    __shared__ float sw[NK * NA];
    __shared__ float sm[256];
    for (int t = threadIdx.x; t < NK * NA; t += 256)
        sw[t] = ((const float*)g_wintra[s])[t];
    __syncthreads();
    const float* crow = cov + ((size_t)s * NA + a) * NA;
    float acc[NK] = {0, 0, 0, 0, 0};
    for (int d = threadIdx.x; d < NA; d += 256) {
        float x = crow[d];
#pragma unroll
        for (int c = 0; c < NK; c++) acc[c] += x * sw[c * NA + d];
    }
    for (int c = 0; c < NK; c++) {
        sm[threadIdx.x] = acc[c]; __syncthreads();
        for (int st = 128; st > 0; st >>= 1) {
            if (threadIdx.x < st) sm[threadIdx.x] += sm[threadIdx.x + st];
            __syncthreads();
        }
        if (threadIdx.x == 0) g_Y[s][a][c] = sm[0];
        __syncthreads();
    }
}

// inter[k][l] = sum_a wintra[k][a] * Y[a][l]
__global__ void __launch_bounds__(NA) k_inter() {
    int s = blockIdx.x, t = threadIdx.x;
    __shared__ float sm[NA];
    for (int kl = 0; kl < NK * NK; kl++) {
        int k = kl / NK, l = kl % NK;
        sm[t] = g_wintra[s][k][t] * g_Y[s][t][l];
        __syncthreads();
        for (int st = 512; st > 0; st >>= 1) {
            if (t < st) sm[t] += sm[t + st];
            __syncthreads();
        }
        if (t == 0) g_inter[s][k][l] = sm[0];
        __syncthreads();
    }
}

// 5x5 inverse (double, partial pivot) + min-var inter weights; 1 warp per sample
__global__ void __launch_bounds__(32) k_winter() {
    int s = blockIdx.x;
    if (threadIdx.x != 0) return;
    double M[NK][2 * NK];
    for (int i = 0; i < NK; i++)
        for (int j = 0; j < NK; j++) {
            M[i][j] = (double)g_inter[s][i][j];
            M[i][NK + j] = (i == j) ? 1.0 : 0.0;
        }
    for (int col = 0; col < NK; col++) {
        int p = col; double bv = fabs(M[col][col]);
        for (int r = col + 1; r < NK; r++) {
            double v = fabs(M[r][col]);
            if (v > bv) { bv = v; p = r; }
        }
        if (p != col)
            for (int j = 0; j < 2 * NK; j++) {
                double tmp = M[col][j]; M[col][j] = M[p][j]; M[p][j] = tmp;
            }
        double pv = M[col][col];
        for (int j = 0; j < 2 * NK; j++) M[col][j] /= pv;
        for (int r = 0; r < NK; r++)
            if (r != col) {
                double f = M[r][col];
                for (int j = 0; j < 2 * NK; j++) M[r][j] -= f * M[col][j];
            }
    }
    double rs[NK], tot = 0.0;
    for (int i = 0; i < NK; i++) {
        double v = 0.0;
        for (int j = 0; j < NK; j++) v += M[i][NK + j];
        rs[i] = v; tot += v;
    }
    for (int i = 0; i < NK; i++) g_winter[s][i] = (float)(rs[i] / tot);
}

// final combine: out[s][a] = sum_c wintra[c][a] * winter[c]
__global__ void __launch_bounds__(NA) k_final(float* __restrict__ out) {
    int s = blockIdx.x, t = threadIdx.x;
    __shared__ float swint[NK];
    if (t < NK) swint[t] = g_winter[s][t];
    __syncthreads();
    float o = 0.f;
#pragma unroll
    for (int c = 0; c < NK; c++) o += g_wintra[s][c][t] * swint[c];
    out[s * NA + t] = o;
}

// ---------------- host: exact JAX threefry init-index reproduction ----------------
// PARTITIONABLE mode (jax_threefry_partitionable=True, the modern default):
//   split(key, shape):  key_i = threefry2x32(key, (hi64(i)=0, lo64(i)=i)), both words
//   random_bits(key, 32, shape): bits_i = o0_i ^ o1_i of threefry2x32(key, (0, i))

static inline void tf2x32(uint32_t k0, uint32_t k1, uint32_t c0, uint32_t c1,
                          uint32_t& o0, uint32_t& o1) {
    uint32_t ks[3] = { k0, k1, k0 ^ k1 ^ 0x1BD11BDAu };
    uint32_t x0 = c0 + ks[0], x1 = c1 + ks[1];
    static const int R[8] = { 13, 15, 26, 6, 17, 29, 16, 24 };
    for (int i = 0; i < 5; i++) {
        const int* r = &R[(i % 2) * 4];
        for (int j = 0; j < 4; j++) {
            x0 += x1;
            x1 = (x1 << r[j]) | (x1 >> (32 - r[j]));
            x1 ^= x0;
        }
        x0 += ks[(i + 1) % 3];
        x1 += ks[(i + 2) % 3] + (uint32_t)(i + 1);
    }
    o0 = x0; o1 = x1;
}

static void compute_init_idx(InitIdx* ii) {
    // jax _shuffle round count: exponent=3,
    // num_rounds = ceil(3 * ln(1024) / ln(2^32-1)) = 1.
    int num_rounds = (int)std::ceil(3.0 * std::log((double)NA) /
                                    std::log(4294967295.0));
    for (int s = 0; s < NS; s++) {
        // keys = split(key(42), 8), foldlike: key_s = threefry((0,42), (0,s))
        uint32_t k0, k1;
        tf2x32(0u, 42u, 0u, (uint32_t)s, k0, k1);

        std::vector<int> vals(NA);
        for (int i = 0; i < NA; i++) vals[i] = i;
        std::vector<std::pair<uint32_t, int>> p(NA);

        for (int r = 0; r < num_rounds; r++) {
            // key, subkey = split(key): foldlike rows = threefry(key, (0,0)), (0,1)
            uint32_t nk0, nk1, sk0, sk1;
            tf2x32(k0, k1, 0u, 0u, nk0, nk1);  // new key (row 0)
            tf2x32(k0, k1, 0u, 1u, sk0, sk1);  // subkey  (row 1)
            k0 = nk0; k1 = nk1;
            // sort_keys = random_bits(subkey, 32, (1024,)): bits_i = o0 ^ o1
            for (int i = 0; i < NA; i++) {
                uint32_t o0, o1;
                tf2x32(sk0, sk1, 0u, (uint32_t)i, o0, o1);
                p[i] = { o0 ^ o1, vals[i] };
            }
            std::stable_sort(p.begin(), p.end(),
                [](const std::pair<uint32_t, int>& x, const std::pair<uint32_t, int>& y) {
                    return x.first < y.first;
                });
            for (int i = 0; i < NA; i++) vals[i] = p[i].second;
        }
        for (int c = 0; c < NK; c++) ii->v[s * NK + c] = vals[c];
    }
}

extern "C" void kernel_launch(void* const* d_in, const int* in_sizes, int n_in,
                              void* d_out, int out_size) {
    (void)in_sizes; (void)n_in; (void)out_size;
    const float* cov = (const float*)d_in[0];
    float* out = (float*)d_out;

    InitIdx ii;
    compute_init_idx(&ii);

    k_prep<<<NS, NA>>>(cov);
    k_corr<<<NS * NA, 256>>>(cov);
    k_initc<<<NS, NA>>>(ii);

    for (int it = 0; it < NIT; it++) {
        k_assign<<<dim3(64, NS), 256>>>();
        k_reduce<<<NS, NA>>>(it);
        k_updA<<<dim3(NCH, NS), 256>>>();
        k_updB<<<NS, NA>>>();
    }

    k_lists<<<NS, 32>>>();
    k_gather<<<dim3(16, NK, NS), 256>>>(cov);
    k_chol<<<dim3(NK, NS), 256>>>();
    k_Y<<<NS * NA, 256>>>(cov);
    k_inter<<<NS, NA>>>();
    k_winter<<<NS, 32>>>();
    k_final<<<NS, NA>>>(out);
}

// round 11
// speedup vs baseline: 16.9292x; 16.9292x over previous
#include <cuda_runtime.h>
#include <cstdint>
#include <cmath>
#include <vector>
#include <algorithm>
#include <utility>

// Problem constants
constexpr int NS  = 8;     // samples
constexpr int NA  = 1024;  // assets
constexpr int NK  = 5;     // clusters
constexpr int NIT = 30;    // max kmeans iterations
constexpr int NCH = 64;    // row-chunks (16 rows each) for centroid partials
constexpr int CGI = 48;    // max CG iterations

// ---------------- device scratch (static: no runtime allocation) ----------------
__device__ float g_corr[NS][NA][NA];      // 32 MB
__device__ float g_rstd[NS][NA];
__device__ float g_xn[NS][NA];
__device__ float g_cent[NS][NK][NA];
__device__ float g_cn[NS][NK];
__device__ int   g_ixs[NS][NA];
__device__ float g_mind[NS][NA];
__device__ float g_prev[NS];
__device__ int   g_flag[NS];
__device__ int   g_cnt[NS][NK];
__device__ float g_part[NS][NCH][NK][NA]; // centroid partial sums (10.5 MB)
__device__ int   g_clidx[NS][NA];
__device__ int   g_cloff[NS][NK];
__device__ int   g_suboff[NS][NK];
__device__ float g_sub[NS][NA * NA + 4096]; // packed padded submatrices
__device__ float g_wintra[NS][NK][NA];
__device__ float g_Y[NS][NA][NK];
__device__ float g_inter[NS][NK][NK];
__device__ float g_winter[NS][NK];

struct InitIdx { int v[NS * NK]; };

// ---------------- kernels ----------------

__global__ void __launch_bounds__(NA) k_prep(const float* __restrict__ cov) {
    int s = blockIdx.x, i = threadIdx.x;
    float d = cov[((size_t)s * NA + i) * NA + i];
    g_rstd[s][i] = rsqrtf(d);
    if (i == 0) { g_flag[s] = 0; g_prev[s] = __int_as_float(0x7f800000); }
}

// corr[s][i][j] = cov/(std_i std_j); also row norms xn (fixed-order tree reduce)
__global__ void __launch_bounds__(256) k_corr(const float* __restrict__ cov) {
    int b = blockIdx.x, s = b >> 10, i = b & (NA - 1);
    const float* row = cov + ((size_t)s * NA + i) * NA;
    float ri = g_rstd[s][i];
    __shared__ float sm[256];
    float acc = 0.f;
    for (int j = threadIdx.x; j < NA; j += 256) {
        float v = row[j] * ri * g_rstd[s][j];
        g_corr[s][i][j] = v;
        acc += v * v;
    }
    sm[threadIdx.x] = acc; __syncthreads();
    for (int st = 128; st > 0; st >>= 1) {
        if (threadIdx.x < st) sm[threadIdx.x] += sm[threadIdx.x + st];
        __syncthreads();
    }
    if (threadIdx.x == 0) g_xn[s][i] = sm[0];
}

__global__ void __launch_bounds__(NA) k_initc(InitIdx ii) {
    int s = blockIdx.x, d = threadIdx.x;
    __shared__ float sm[NA];
    float cv[NK];
#pragma unroll
    for (int c = 0; c < NK; c++) {
        int idx = ii.v[s * NK + c];
        cv[c] = g_corr[s][idx][d];
        g_cent[s][c][d] = cv[c];
    }
    for (int c = 0; c < NK; c++) {
        sm[d] = cv[c] * cv[c]; __syncthreads();
        for (int st = 512; st > 0; st >>= 1) {
            if (d < st) sm[d] += sm[d + st];
            __syncthreads();
        }
        if (d == 0) g_cn[s][c] = sm[0];
        __syncthreads();
    }
}

// FUSED: distances + argmin + centroid partial sums for this block's 16 rows.
// 8 warps x 2 rows; second pass over the same 16 rows hits L1.
__global__ void __launch_bounds__(256) k_assign_upd() {
    int s = blockIdx.y;
    if (g_flag[s]) return;
    __shared__ float sc[NK * NA];
    __shared__ float scn[NK];
    __shared__ int sixs[16];
    for (int t = threadIdx.x; t < NK * NA; t += 256)
        sc[t] = ((const float*)g_cent[s])[t];
    if (threadIdx.x < NK) scn[threadIdx.x] = g_cn[s][threadIdx.x];
    __syncthreads();
    int warp = threadIdx.x >> 5, lane = threadIdx.x & 31;
    int base = blockIdx.x * 16;
    for (int rr = 0; rr < 2; rr++) {
        int lrow = warp * 2 + rr;
        int row = base + lrow;
        const float* xr = g_corr[s][row];
        float a0 = 0, a1 = 0, a2 = 0, a3 = 0, a4 = 0;
        for (int dd = lane; dd < NA; dd += 32) {
            float x = xr[dd];
            a0 += x * sc[0 * NA + dd]; a1 += x * sc[1 * NA + dd];
            a2 += x * sc[2 * NA + dd]; a3 += x * sc[3 * NA + dd];
            a4 += x * sc[4 * NA + dd];
        }
        for (int off = 16; off > 0; off >>= 1) {
            a0 += __shfl_down_sync(0xffffffffu, a0, off);
            a1 += __shfl_down_sync(0xffffffffu, a1, off);
            a2 += __shfl_down_sync(0xffffffffu, a2, off);
            a3 += __shfl_down_sync(0xffffffffu, a3, off);
            a4 += __shfl_down_sync(0xffffffffu, a4, off);
        }
        if (lane == 0) {
            float xn = g_xn[s][row];
            float d0 = fmaxf(xn + scn[0] - 2.f * a0, 0.f);
            float d1 = fmaxf(xn + scn[1] - 2.f * a1, 0.f);
            float d2 = fmaxf(xn + scn[2] - 2.f * a2, 0.f);
            float d3 = fmaxf(xn + scn[3] - 2.f * a3, 0.f);
            float d4 = fmaxf(xn + scn[4] - 2.f * a4, 0.f);
            float best = d0; int bi = 0;
            if (d1 < best) { best = d1; bi = 1; }
            if (d2 < best) { best = d2; bi = 2; }
            if (d3 < best) { best = d3; bi = 3; }
            if (d4 < best) { best = d4; bi = 4; }
            g_ixs[s][row] = bi;
            g_mind[s][row] = best;
            sixs[lrow] = bi;
        }
    }
    __syncthreads();
    // centroid partial sums over this block's 16 rows (L1-resident)
    int t = threadIdx.x;
    float acc[NK][4];
#pragma unroll
    for (int c = 0; c < NK; c++)
#pragma unroll
        for (int j = 0; j < 4; j++) acc[c][j] = 0.f;
    for (int ii = 0; ii < 16; ii++) {
        int row = base + ii;
        int ix = sixs[ii];
        const float* xr = g_corr[s][row];
        float m[NK];
#pragma unroll
        for (int c = 0; c < NK; c++) m[c] = (ix == c) ? 1.f : 0.f;
#pragma unroll
        for (int j = 0; j < 4; j++) {
            float x = xr[t + 256 * j];
#pragma unroll
            for (int c = 0; c < NK; c++) acc[c][j] += m[c] * x;
        }
    }
#pragma unroll
    for (int c = 0; c < NK; c++)
#pragma unroll
        for (int j = 0; j < 4; j++)
            g_part[s][blockIdx.x][c][t + 256 * j] = acc[c][j];
}

// potential (fixed-order tree), counts (int atomics: deterministic), convergence
__global__ void __launch_bounds__(NA) k_reduce(int iter) {
    int s = blockIdx.x, t = threadIdx.x;
    if (g_flag[s]) return;
    __shared__ float sm[NA];
    __shared__ int scnt[NK];
    if (t < NK) scnt[t] = 0;
    __syncthreads();
    atomicAdd(&scnt[g_ixs[s][t]], 1);
    sm[t] = g_mind[s][t];
    __syncthreads();
    for (int st = 512; st > 0; st >>= 1) {
        if (t < st) sm[t] += sm[t + st];
        __syncthreads();
    }
    if (t < NK) g_cnt[s][t] = scnt[t];
    if (t == 0) {
        float pot = sm[0];
        if (iter > 0 && fabsf(pot - g_prev[s]) < 1e-5f) g_flag[s] = 1;
        g_prev[s] = pot;
    }
}

// combine partials -> new centers; center norms via fixed-order reductions
__global__ void __launch_bounds__(NA) k_updB() {
    int s = blockIdx.x;
    if (g_flag[s]) return;
    int d = threadIdx.x;
    __shared__ float sm[NA];
    float nc[NK];
#pragma unroll
    for (int c = 0; c < NK; c++) {
        float sum = 0.f;
        for (int ch = 0; ch < NCH; ch++) sum += g_part[s][ch][c][d];
        int cnt = g_cnt[s][c];
        float v = (cnt > 0) ? sum / (float)cnt : g_cent[s][c][d];
        nc[c] = v;
        g_cent[s][c][d] = v;
    }
    for (int c = 0; c < NK; c++) {
        sm[d] = nc[c] * nc[c]; __syncthreads();
        for (int st = 512; st > 0; st >>= 1) {
            if (d < st) sm[d] += sm[d + st];
            __syncthreads();
        }
        if (d == 0) g_cn[s][c] = sm[0];
        __syncthreads();
    }
}

// cluster member lists + packed (4-padded-stride) submatrix offsets
__global__ void __launch_bounds__(32) k_lists() {
    int s = blockIdx.x;
    if (threadIdx.x != 0) return;
    int off = 0, soff = 0;
    int pos[NK];
    for (int k = 0; k < NK; k++) {
        g_cloff[s][k] = off;
        g_suboff[s][k] = soff;
        pos[k] = off;
        int n = g_cnt[s][k];
        int nn = (n + 3) & ~3;
        off += n; soff += n * nn;
    }
    for (int i = 0; i < NA; i++) {
        int k = g_ixs[s][i];
        g_clidx[s][pos[k]++] = i;
    }
}

// gather per-cluster sub-covariance with padded row stride (zeros in pad cols)
__global__ void __launch_bounds__(256) k_gather(const float* __restrict__ cov) {
    int s = blockIdx.z, k = blockIdx.y;
    int n = g_cnt[s][k];
    if (n == 0) return;
    int nn = (n + 3) & ~3;
    __shared__ int sidx[NA];
    int off = g_cloff[s][k];
    for (int t = threadIdx.x; t < n; t += 256) sidx[t] = g_clidx[s][off + t];
    __syncthreads();
    float* sub = &g_sub[s][g_suboff[s][k]];
    for (int r = blockIdx.x; r < n; r += gridDim.x) {
        const float* crow = cov + ((size_t)s * NA + sidx[r]) * NA;
        for (int c = threadIdx.x; c < nn; c += 256)
            sub[(size_t)r * nn + c] = (c < n) ? crow[sidx[c]] : 0.f;
    }
}

// Conjugate gradient: solve Sigma_cc w = 1; scatter w/sum(w).
// One CTA (1024 threads) per (s,k); vectors in smem; matrix in L2.
__global__ void __launch_bounds__(1024) k_cg() {
    int s = blockIdx.y, k = blockIdx.x, t = threadIdx.x;
    for (int i = t; i < NA; i += 1024) g_wintra[s][k][i] = 0.f;
    int n = g_cnt[s][k];
    if (n == 0) return;
    int nn = (n + 3) & ~3;
    const float* A = &g_sub[s][g_suboff[s][k]];

    __shared__ float4 s_p4[NA / 4];
    float* s_p = (float*)s_p4;
    __shared__ float s_x[NA], s_r[NA], s_ap[NA];
    __shared__ float s_red[1024];

    for (int i = t; i < nn; i += 1024) s_p[i] = (i < n) ? 1.f : 0.f;
    if (t < n) { s_x[t] = 0.f; s_r[t] = 1.f; }
    float rs_old = (float)n;
    __syncthreads();

    int warp = t >> 5, lane = t & 31;
    int nn4 = nn >> 2;

    for (int iter = 0; iter < CGI; iter++) {
        // Ap = A * p  (warp per row, float4 coalesced)
        for (int row = warp; row < n; row += 32) {
            const float4* Ar = (const float4*)(A + (size_t)row * nn);
            float acc = 0.f;
#pragma unroll 8
            for (int j = lane; j < nn4; j += 32) {
                float4 a = Ar[j], pp = s_p4[j];
                acc += a.x * pp.x + a.y * pp.y + a.z * pp.z + a.w * pp.w;
            }
            for (int off = 16; off > 0; off >>= 1)
                acc += __shfl_down_sync(0xffffffffu, acc, off);
            if (lane == 0) s_ap[row] = acc;
        }
        __syncthreads();
        // pAp
        s_red[t] = (t < n) ? s_p[t] * s_ap[t] : 0.f;
        __syncthreads();
        for (int st = 512; st > 0; st >>= 1) {
            if (t < st) s_red[t] += s_red[t + st];
            __syncthreads();
        }
        float alpha = rs_old / s_red[0];
        __syncthreads();
        if (t < n) {
            s_x[t] += alpha * s_p[t];
            s_r[t] -= alpha * s_ap[t];
        }
        // rs_new
        s_red[t] = (t < n) ? s_r[t] * s_r[t] : 0.f;
        __syncthreads();
        for (int st = 512; st > 0; st >>= 1) {
            if (t < st) s_red[t] += s_red[t + st];
            __syncthreads();
        }
        float rs_new = s_red[0];
        __syncthreads();
        float beta = rs_new / rs_old;
        rs_old = rs_new;
        if (t < n) s_p[t] = s_r[t] + beta * s_p[t];
        __syncthreads();
        if (rs_new < 1e-12f * (float)n) break;   // deterministic, all-thread-agree
    }

    // denom = sum(x); scatter
    s_red[t] = (t < n) ? s_x[t] : 0.f;
    __syncthreads();
    for (int st = 512; st > 0; st >>= 1) {
        if (t < st) s_red[t] += s_red[t + st];
        __syncthreads();
    }
    float denom = s_red[0];
    int off = g_cloff[s][k];
    if (t < n)
        g_wintra[s][k][g_clidx[s][off + t]] = s_x[t] / denom;
}

// Y[s][a][l] = sum_b cov[a][b] * wintra[l][b]
__global__ void __launch_bounds__(256) k_Y(const float* __restrict__ cov) {
    int b = blockIdx.x, s = b >> 10, a = b & (NA - 1);
    __shared__ float sw[NK * NA];
    __shared__ float sm[256];
    for (int t = threadIdx.x; t < NK * NA; t += 256)
        sw[t] = ((const float*)g_wintra[s])[t];
    __syncthreads();
    const float* crow = cov + ((size_t)s * NA + a) * NA;
    float acc[NK] = {0, 0, 0, 0, 0};
    for (int d = threadIdx.x; d < NA; d += 256) {
        float x = crow[d];
#pragma unroll
        for (int c = 0; c < NK; c++) acc[c] += x * sw[c * NA + d];
    }
    for (int c = 0; c < NK; c++) {
        sm[threadIdx.x] = acc[c]; __syncthreads();
        for (int st = 128; st > 0; st >>= 1) {
            if (threadIdx.x < st) sm[threadIdx.x] += sm[threadIdx.x + st];
            __syncthreads();
        }
        if (threadIdx.x == 0) g_Y[s][a][c] = sm[0];
        __syncthreads();
    }
}

// inter[k][l] = sum_a wintra[k][a] * Y[a][l]
__global__ void __launch_bounds__(NA) k_inter() {
    int s = blockIdx.x, t = threadIdx.x;
    __shared__ float sm[NA];
    for (int kl = 0; kl < NK * NK; kl++) {
        int k = kl / NK, l = kl % NK;
        sm[t] = g_wintra[s][k][t] * g_Y[s][t][l];
        __syncthreads();
        for (int st = 512; st > 0; st >>= 1) {
            if (t < st) sm[t] += sm[t + st];
            __syncthreads();
        }
        if (t == 0) g_inter[s][k][l] = sm[0];
        __syncthreads();
    }
}

// 5x5 inverse (double, partial pivot) + min-var inter weights; 1 warp per sample
__global__ void __launch_bounds__(32) k_winter() {
    int s = blockIdx.x;
    if (threadIdx.x != 0) return;
    double M[NK][2 * NK];
    for (int i = 0; i < NK; i++)
        for (int j = 0; j < NK; j++) {
            M[i][j] = (double)g_inter[s][i][j];
            M[i][NK + j] = (i == j) ? 1.0 : 0.0;
        }
    for (int col = 0; col < NK; col++) {
        int p = col; double bv = fabs(M[col][col]);
        for (int r = col + 1; r < NK; r++) {
            double v = fabs(M[r][col]);
            if (v > bv) { bv = v; p = r; }
        }
        if (p != col)
            for (int j = 0; j < 2 * NK; j++) {
                double tmp = M[col][j]; M[col][j] = M[p][j]; M[p][j] = tmp;
            }
        double pv = M[col][col];
        for (int j = 0; j < 2 * NK; j++) M[col][j] /= pv;
        for (int r = 0; r < NK; r++)
            if (r != col) {
                double f = M[r][col];
                for (int j = 0; j < 2 * NK; j++) M[r][j] -= f * M[col][j];
            }
    }
    double rs[NK], tot = 0.0;
    for (int i = 0; i < NK; i++) {
        double v = 0.0;
        for (int j = 0; j < NK; j++) v += M[i][NK + j];
        rs[i] = v; tot += v;
    }
    for (int i = 0; i < NK; i++) g_winter[s][i] = (float)(rs[i] / tot);
}

// final combine: out[s][a] = sum_c wintra[c][a] * winter[c]
__global__ void __launch_bounds__(NA) k_final(float* __restrict__ out) {
    int s = blockIdx.x, t = threadIdx.x;
    __shared__ float swint[NK];
    if (t < NK) swint[t] = g_winter[s][t];
    __syncthreads();
    float o = 0.f;
#pragma unroll
    for (int c = 0; c < NK; c++) o += g_wintra[s][c][t] * swint[c];
    out[s * NA + t] = o;
}

// ---------------- host: exact JAX threefry init-index reproduction ----------------
// PARTITIONABLE mode (jax_threefry_partitionable=True, the modern default):
//   split(key, shape):  key_i = threefry2x32(key, (0, i)), both output words
//   random_bits(key, 32, shape): bits_i = o0_i ^ o1_i of threefry2x32(key, (0, i))

static inline void tf2x32(uint32_t k0, uint32_t k1, uint32_t c0, uint32_t c1,
                          uint32_t& o0, uint32_t& o1) {
    uint32_t ks[3] = { k0, k1, k0 ^ k1 ^ 0x1BD11BDAu };
    uint32_t x0 = c0 + ks[0], x1 = c1 + ks[1];
    static const int R[8] = { 13, 15, 26, 6, 17, 29, 16, 24 };
    for (int i = 0; i < 5; i++) {
        const int* r = &R[(i % 2) * 4];
        for (int j = 0; j < 4; j++) {
            x0 += x1;
            x1 = (x1 << r[j]) | (x1 >> (32 - r[j]));
            x1 ^= x0;
        }
        x0 += ks[(i + 1) % 3];
        x1 += ks[(i + 2) % 3] + (uint32_t)(i + 1);
    }
    o0 = x0; o1 = x1;
}

static void compute_init_idx(InitIdx* ii) {
    int num_rounds = (int)std::ceil(3.0 * std::log((double)NA) /
                                    std::log(4294967295.0));  // = 1
    for (int s = 0; s < NS; s++) {
        uint32_t k0, k1;
        tf2x32(0u, 42u, 0u, (uint32_t)s, k0, k1);   // keys = split(key(42), 8)

        std::vector<int> vals(NA);
        for (int i = 0; i < NA; i++) vals[i] = i;
        std::vector<std::pair<uint32_t, int>> p(NA);

        for (int r = 0; r < num_rounds; r++) {
            uint32_t nk0, nk1, sk0, sk1;
            tf2x32(k0, k1, 0u, 0u, nk0, nk1);  // new key
            tf2x32(k0, k1, 0u, 1u, sk0, sk1);  // subkey
            k0 = nk0; k1 = nk1;
            for (int i = 0; i < NA; i++) {
                uint32_t o0, o1;
                tf2x32(sk0, sk1, 0u, (uint32_t)i, o0, o1);
                p[i] = { o0 ^ o1, vals[i] };
            }
            std::stable_sort(p.begin(), p.end(),
                [](const std::pair<uint32_t, int>& x, const std::pair<uint32_t, int>& y) {
                    return x.first < y.first;
                });
            for (int i = 0; i < NA; i++) vals[i] = p[i].second;
        }
        for (int c = 0; c < NK; c++) ii->v[s * NK + c] = vals[c];
    }
}

extern "C" void kernel_launch(void* const* d_in, const int* in_sizes, int n_in,
                              void* d_out, int out_size) {
    (void)in_sizes; (void)n_in; (void)out_size;
    const float* cov = (const float*)d_in[0];
    float* out = (float*)d_out;

    InitIdx ii;
    compute_init_idx(&ii);

    k_prep<<<NS, NA>>>(cov);
    k_corr<<<NS * NA, 256>>>(cov);
    k_initc<<<NS, NA>>>(ii);

    for (int it = 0; it < NIT; it++) {
        k_assign_upd<<<dim3(NCH, NS), 256>>>();
        k_reduce<<<NS, NA>>>(it);
        k_updB<<<NS, NA>>>();
    }

    k_lists<<<NS, 32>>>();
    k_gather<<<dim3(16, NK, NS), 256>>>(cov);
    k_cg<<<dim3(NK, NS), 1024>>>();
    k_Y<<<NS * NA, 256>>>(cov);
    k_inter<<<NS, NA>>>();
    k_winter<<<NS, 32>>>();
    k_final<<<NS, NA>>>(out);
}

// round 13
// speedup vs baseline: 23.1415x; 1.3670x over previous
#include <cuda_runtime.h>
#include <cstdint>
#include <cmath>
#include <vector>
#include <algorithm>
#include <utility>

// Problem constants
constexpr int NS  = 8;     // samples
constexpr int NA  = 1024;  // assets
constexpr int NK  = 5;     // clusters
constexpr int NIT = 30;    // max kmeans iterations
constexpr int NCH = 64;    // row-chunks (16 rows each) for centroid partials
constexpr int CGI = 48;    // max CG iterations

// ---------------- device scratch (static: no runtime allocation) ----------------
__device__ float g_corr[NS][NA][NA];      // 32 MB
__device__ float g_rstd[NS][NA];
__device__ float g_xn[NS][NA];
__device__ float g_cent[NS][NK][NA];
__device__ float g_cn[NS][NK];
__device__ int   g_ixs[NS][NA];
__device__ float g_mind[NS][NA];
__device__ float g_prev[NS];
__device__ int   g_flag[NS];
__device__ int   g_cnt[NS][NK];
__device__ float g_part[NS][NCH][NK][NA]; // centroid partial sums (10.5 MB)
__device__ int   g_clidx[NS][NA];
__device__ int   g_cloff[NS][NK];
__device__ int   g_suboff[NS][NK];
__device__ float g_sub[NS][NA * NA + 4096]; // packed padded submatrices
__device__ float g_wintra[NS][NK][NA];
__device__ float g_Y[NS][NA][NK];
__device__ float g_inter[NS][NK][NK];
__device__ float g_winter[NS][NK];

struct InitIdx { int v[NS * NK]; };

// ---------------- kernels ----------------

__global__ void __launch_bounds__(NA) k_prep(const float* __restrict__ cov) {
    int s = blockIdx.x, i = threadIdx.x;
    float d = cov[((size_t)s * NA + i) * NA + i];
    g_rstd[s][i] = rsqrtf(d);
    if (i == 0) { g_flag[s] = 0; g_prev[s] = __int_as_float(0x7f800000); }
}

// corr[s][i][j] = cov/(std_i std_j); also row norms xn (fixed-order tree reduce)
__global__ void __launch_bounds__(256) k_corr(const float* __restrict__ cov) {
    int b = blockIdx.x, s = b >> 10, i = b & (NA - 1);
    const float* row = cov + ((size_t)s * NA + i) * NA;
    float ri = g_rstd[s][i];
    __shared__ float sm[256];
    float acc = 0.f;
    for (int j = threadIdx.x; j < NA; j += 256) {
        float v = row[j] * ri * g_rstd[s][j];
        g_corr[s][i][j] = v;
        acc += v * v;
    }
    sm[threadIdx.x] = acc; __syncthreads();
    for (int st = 128; st > 0; st >>= 1) {
        if (threadIdx.x < st) sm[threadIdx.x] += sm[threadIdx.x + st];
        __syncthreads();
    }
    if (threadIdx.x == 0) g_xn[s][i] = sm[0];
}

__global__ void __launch_bounds__(NA) k_initc(InitIdx ii) {
    int s = blockIdx.x, d = threadIdx.x;
    __shared__ float sm[NA];
    float cv[NK];
#pragma unroll
    for (int c = 0; c < NK; c++) {
        int idx = ii.v[s * NK + c];
        cv[c] = g_corr[s][idx][d];
        g_cent[s][c][d] = cv[c];
    }
    for (int c = 0; c < NK; c++) {
        sm[d] = cv[c] * cv[c]; __syncthreads();
        for (int st = 512; st > 0; st >>= 1) {
            if (d < st) sm[d] += sm[d + st];
            __syncthreads();
        }
        if (d == 0) g_cn[s][c] = sm[0];
        __syncthreads();
    }
}

// FUSED assign + centroid partials. 512 threads = 16 warps; 16 rows per block.
// Warp w: row-pair p = w>>1 (rows base+2p, base+2p+1), dim-half h = w&1.
// Each warp processes 2 rows x 512 dims with float4; center value reused for
// both rows (halves smem traffic). Cross-half combine via small smem tile.
__global__ void __launch_bounds__(512) k_assign_upd() {
    int s = blockIdx.y;
    if (g_flag[s]) return;
    __shared__ float4 sc4[NK * 256];        // centers as float4 (20 KB)
    __shared__ float scn[NK];
    __shared__ float s_pp[16][10];          // per-warp partials (2 rows x 5)
    __shared__ int sixs[16];
    {
        const float4* cg = (const float4*)g_cent[s];
        for (int t = threadIdx.x; t < NK * 256; t += 512) sc4[t] = cg[t];
        if (threadIdx.x < NK) scn[threadIdx.x] = g_cn[s][threadIdx.x];
    }
    __syncthreads();
    int warp = threadIdx.x >> 5, lane = threadIdx.x & 31;
    int pair = warp >> 1, half = warp & 1;
    int base = blockIdx.x * 16;
    {
        int r0 = base + pair * 2, r1 = r0 + 1;
        const float4* xr0 = (const float4*)g_corr[s][r0];
        const float4* xr1 = (const float4*)g_corr[s][r1];
        float a0[NK] = {0, 0, 0, 0, 0}, a1[NK] = {0, 0, 0, 0, 0};
        int j0 = half * 128 + lane;
#pragma unroll
        for (int i = 0; i < 4; i++) {
            int j = j0 + 32 * i;
            float4 x0 = xr0[j], x1 = xr1[j];
#pragma unroll
            for (int c = 0; c < NK; c++) {
                float4 cv = sc4[c * 256 + j];
                a0[c] += x0.x * cv.x + x0.y * cv.y + x0.z * cv.z + x0.w * cv.w;
                a1[c] += x1.x * cv.x + x1.y * cv.y + x1.z * cv.z + x1.w * cv.w;
            }
        }
#pragma unroll
        for (int c = 0; c < NK; c++) {
            for (int off = 16; off > 0; off >>= 1) {
                a0[c] += __shfl_down_sync(0xffffffffu, a0[c], off);
                a1[c] += __shfl_down_sync(0xffffffffu, a1[c], off);
            }
        }
        if (lane == 0) {
#pragma unroll
            for (int c = 0; c < NK; c++) {
                s_pp[warp][c] = a0[c];
                s_pp[warp][5 + c] = a1[c];
            }
        }
    }
    __syncthreads();
    if (threadIdx.x < 16) {
        int lrow = threadIdx.x;
        int p = lrow >> 1, rowin = lrow & 1;
        int row = base + lrow;
        float xn = g_xn[s][row];
        float best = __int_as_float(0x7f800000); int bi = 0;
#pragma unroll
        for (int c = 0; c < NK; c++) {
            float a = s_pp[2 * p][rowin * 5 + c] + s_pp[2 * p + 1][rowin * 5 + c];
            float d = fmaxf(xn + scn[c] - 2.f * a, 0.f);
            if (d < best) { best = d; bi = c; }
        }
        g_ixs[s][row] = bi;
        g_mind[s][row] = best;
        sixs[lrow] = bi;
    }
    __syncthreads();
    // centroid partial sums over this block's 16 rows; thread owns 2 dims
    int t = threadIdx.x;
    float acc[NK][2];
#pragma unroll
    for (int c = 0; c < NK; c++) { acc[c][0] = 0.f; acc[c][1] = 0.f; }
    for (int ii = 0; ii < 16; ii++) {
        int row = base + ii;
        int ix = sixs[ii];
        const float* xr = g_corr[s][row];
        float m[NK];
#pragma unroll
        for (int c = 0; c < NK; c++) m[c] = (ix == c) ? 1.f : 0.f;
        float x0 = xr[t], x1 = xr[t + 512];
#pragma unroll
        for (int c = 0; c < NK; c++) {
            acc[c][0] += m[c] * x0;
            acc[c][1] += m[c] * x1;
        }
    }
#pragma unroll
    for (int c = 0; c < NK; c++) {
        g_part[s][blockIdx.x][c][t] = acc[c][0];
        g_part[s][blockIdx.x][c][t + 512] = acc[c][1];
    }
}

// Per-(s,k) block: combine partials -> new center + norm; own count from ixs.
// Block (s, k=0) additionally computes potential and convergence flag.
__global__ void __launch_bounds__(NA) k_finishB(int iter) {
    int k = blockIdx.x, s = blockIdx.y, t = threadIdx.x;
    if (g_flag[s]) return;
    __shared__ float s_red[NA];
    __shared__ float s_cnt;
    // count of members in cluster k (exact integer arithmetic in float)
    int myix = g_ixs[s][t];
    s_red[t] = (myix == k) ? 1.f : 0.f;
    __syncthreads();
    for (int st = 512; st > 0; st >>= 1) {
        if (t < st) s_red[t] += s_red[t + st];
        __syncthreads();
    }
    if (t == 0) s_cnt = s_red[0];
    __syncthreads();
    float cntf = s_cnt;
    // combine partial sums (fixed ascending chunk order)
    float sum = 0.f;
#pragma unroll 8
    for (int ch = 0; ch < NCH; ch++) sum += g_part[s][ch][k][t];
    float v = (cntf > 0.f) ? sum / cntf : g_cent[s][k][t];
    g_cent[s][k][t] = v;
    __syncthreads();
    s_red[t] = v * v;
    __syncthreads();
    for (int st = 512; st > 0; st >>= 1) {
        if (t < st) s_red[t] += s_red[t + st];
        __syncthreads();
    }
    if (t == 0) g_cn[s][k] = s_red[0];
    if (k == 0) {
        __syncthreads();
        s_red[t] = g_mind[s][t];
        __syncthreads();
        for (int st = 512; st > 0; st >>= 1) {
            if (t < st) s_red[t] += s_red[t + st];
            __syncthreads();
        }
        if (t == 0) {
            float pot = s_red[0];
            if (iter > 0 && fabsf(pot - g_prev[s]) < 1e-5f) g_flag[s] = 1;
            g_prev[s] = pot;
        }
    }
}

// cluster member lists + counts + packed (4-padded-stride) submatrix offsets
__global__ void __launch_bounds__(32) k_lists() {
    int s = blockIdx.x;
    if (threadIdx.x != 0) return;
    int cnt[NK];
    for (int k = 0; k < NK; k++) cnt[k] = 0;
    for (int i = 0; i < NA; i++) cnt[g_ixs[s][i]]++;
    int off = 0, soff = 0;
    int pos[NK];
    for (int k = 0; k < NK; k++) {
        g_cnt[s][k] = cnt[k];
        g_cloff[s][k] = off;
        g_suboff[s][k] = soff;
        pos[k] = off;
        int n = cnt[k];
        int nn = (n + 3) & ~3;
        off += n; soff += n * nn;
    }
    for (int i = 0; i < NA; i++) {
        int k = g_ixs[s][i];
        g_clidx[s][pos[k]++] = i;
    }
}

// gather per-cluster sub-covariance with padded row stride (zeros in pad cols)
__global__ void __launch_bounds__(256) k_gather(const float* __restrict__ cov) {
    int s = blockIdx.z, k = blockIdx.y;
    int n = g_cnt[s][k];
    if (n == 0) return;
    int nn = (n + 3) & ~3;
    __shared__ int sidx[NA];
    int off = g_cloff[s][k];
    for (int t = threadIdx.x; t < n; t += 256) sidx[t] = g_clidx[s][off + t];
    __syncthreads();
    float* sub = &g_sub[s][g_suboff[s][k]];
    for (int r = blockIdx.x; r < n; r += gridDim.x) {
        const float* crow = cov + ((size_t)s * NA + sidx[r]) * NA;
        for (int c = threadIdx.x; c < nn; c += 256)
            sub[(size_t)r * nn + c] = (c < n) ? crow[sidx[c]] : 0.f;
    }
}

// Conjugate gradient: solve Sigma_cc w = 1; scatter w/sum(w).
// One CTA (1024 threads) per (s,k); vectors in smem; matrix in L2.
__global__ void __launch_bounds__(1024) k_cg() {
    int s = blockIdx.y, k = blockIdx.x, t = threadIdx.x;
    for (int i = t; i < NA; i += 1024) g_wintra[s][k][i] = 0.f;
    int n = g_cnt[s][k];
    if (n == 0) return;
    int nn = (n + 3) & ~3;
    const float* A = &g_sub[s][g_suboff[s][k]];

    __shared__ float4 s_p4[NA / 4];
    float* s_p = (float*)s_p4;
    __shared__ float s_x[NA], s_r[NA], s_ap[NA];
    __shared__ float s_red[1024];

    for (int i = t; i < nn; i += 1024) s_p[i] = (i < n) ? 1.f : 0.f;
    if (t < n) { s_x[t] = 0.f; s_r[t] = 1.f; }
    float rs_old = (float)n;
    __syncthreads();

    int warp = t >> 5, lane = t & 31;
    int nn4 = nn >> 2;

    for (int iter = 0; iter < CGI; iter++) {
        for (int row = warp; row < n; row += 32) {
            const float4* Ar = (const float4*)(A + (size_t)row * nn);
            float acc = 0.f;
#pragma unroll 8
            for (int j = lane; j < nn4; j += 32) {
                float4 a = Ar[j], pp = s_p4[j];
                acc += a.x * pp.x + a.y * pp.y + a.z * pp.z + a.w * pp.w;
            }
            for (int off = 16; off > 0; off >>= 1)
                acc += __shfl_down_sync(0xffffffffu, acc, off);
            if (lane == 0) s_ap[row] = acc;
        }
        __syncthreads();
        s_red[t] = (t < n) ? s_p[t] * s_ap[t] : 0.f;
        __syncthreads();
        for (int st = 512; st > 0; st >>= 1) {
            if (t < st) s_red[t] += s_red[t + st];
            __syncthreads();
        }
        float alpha = rs_old / s_red[0];
        __syncthreads();
        if (t < n) {
            s_x[t] += alpha * s_p[t];
            s_r[t] -= alpha * s_ap[t];
        }
        s_red[t] = (t < n) ? s_r[t] * s_r[t] : 0.f;
        __syncthreads();
        for (int st = 512; st > 0; st >>= 1) {
            if (t < st) s_red[t] += s_red[t + st];
            __syncthreads();
        }
        float rs_new = s_red[0];
        __syncthreads();
        float beta = rs_new / rs_old;
        rs_old = rs_new;
        if (t < n) s_p[t] = s_r[t] + beta * s_p[t];
        __syncthreads();
        if (rs_new < 1e-12f * (float)n) break;   // deterministic, all-thread-agree
    }

    s_red[t] = (t < n) ? s_x[t] : 0.f;
    __syncthreads();
    for (int st = 512; st > 0; st >>= 1) {
        if (t < st) s_red[t] += s_red[t + st];
        __syncthreads();
    }
    float denom = s_red[0];
    int off = g_cloff[s][k];
    if (t < n)
        g_wintra[s][k][g_clidx[s][off + t]] = s_x[t] / denom;
}

// Y[s][a][l] = sum_b cov[a][b] * wintra[l][b]
__global__ void __launch_bounds__(256) k_Y(const float* __restrict__ cov) {
    int b = blockIdx.x, s = b >> 10, a = b & (NA - 1);
    __shared__ float sw[NK * NA];
    __shared__ float sm[256];
    for (int t = threadIdx.x; t < NK * NA; t += 256)
        sw[t] = ((const float*)g_wintra[s])[t];
    __syncthreads();
    const float* crow = cov + ((size_t)s * NA + a) * NA;
    float acc[NK] = {0, 0, 0, 0, 0};
    for (int d = threadIdx.x; d < NA; d += 256) {
        float x = crow[d];
#pragma unroll
        for (int c = 0; c < NK; c++) acc[c] += x * sw[c * NA + d];
    }
    for (int c = 0; c < NK; c++) {
        sm[threadIdx.x] = acc[c]; __syncthreads();
        for (int st = 128; st > 0; st >>= 1) {
            if (threadIdx.x < st) sm[threadIdx.x] += sm[threadIdx.x + st];
            __syncthreads();
        }
        if (threadIdx.x == 0) g_Y[s][a][c] = sm[0];
        __syncthreads();
    }
}

// inter[k][l] = sum_a wintra[k][a] * Y[a][l]
__global__ void __launch_bounds__(NA) k_inter() {
    int s = blockIdx.x, t = threadIdx.x;
    __shared__ float sm[NA];
    for (int kl = 0; kl < NK * NK; kl++) {
        int k = kl / NK, l = kl % NK;
        sm[t] = g_wintra[s][k][t] * g_Y[s][t][l];
        __syncthreads();
        for (int st = 512; st > 0; st >>= 1) {
            if (t < st) sm[t] += sm[t + st];
            __syncthreads();
        }
        if (t == 0) g_inter[s][k][l] = sm[0];
        __syncthreads();
    }
}

// 5x5 inverse (double, partial pivot) + min-var inter weights; 1 warp per sample
__global__ void __launch_bounds__(32) k_winter() {
    int s = blockIdx.x;
    if (threadIdx.x != 0) return;
    double M[NK][2 * NK];
    for (int i = 0; i < NK; i++)
        for (int j = 0; j < NK; j++) {
            M[i][j] = (double)g_inter[s][i][j];
            M[i][NK + j] = (i == j) ? 1.0 : 0.0;
        }
    for (int col = 0; col < NK; col++) {
        int p = col; double bv = fabs(M[col][col]);
        for (int r = col + 1; r < NK; r++) {
            double v = fabs(M[r][col]);
            if (v > bv) { bv = v; p = r; }
        }
        if (p != col)
            for (int j = 0; j < 2 * NK; j++) {
                double tmp = M[col][j]; M[col][j] = M[p][j]; M[p][j] = tmp;
            }
        double pv = M[col][col];
        for (int j = 0; j < 2 * NK; j++) M[col][j] /= pv;
        for (int r = 0; r < NK; r++)
            if (r != col) {
                double f = M[r][col];
                for (int j = 0; j < 2 * NK; j++) M[r][j] -= f * M[col][j];
            }
    }
    double rs[NK], tot = 0.0;
    for (int i = 0; i < NK; i++) {
        double v = 0.0;
        for (int j = 0; j < NK; j++) v += M[i][NK + j];
        rs[i] = v; tot += v;
    }
    for (int i = 0; i < NK; i++) g_winter[s][i] = (float)(rs[i] / tot);
}

// final combine: out[s][a] = sum_c wintra[c][a] * winter[c]
__global__ void __launch_bounds__(NA) k_final(float* __restrict__ out) {
    int s = blockIdx.x, t = threadIdx.x;
    __shared__ float swint[NK];
    if (t < NK) swint[t] = g_winter[s][t];
    __syncthreads();
    float o = 0.f;
#pragma unroll
    for (int c = 0; c < NK; c++) o += g_wintra[s][c][t] * swint[c];
    out[s * NA + t] = o;
}

// ---------------- host: exact JAX threefry init-index reproduction ----------------
// PARTITIONABLE mode (jax_threefry_partitionable=True, the modern default):
//   split(key, shape):  key_i = threefry2x32(key, (0, i)), both output words
//   random_bits(key, 32, shape): bits_i = o0_i ^ o1_i of threefry2x32(key, (0, i))

static inline void tf2x32(uint32_t k0, uint32_t k1, uint32_t c0, uint32_t c1,
                          uint32_t& o0, uint32_t& o1) {
    uint32_t ks[3] = { k0, k1, k0 ^ k1 ^ 0x1BD11BDAu };
    uint32_t x0 = c0 + ks[0], x1 = c1 + ks[1];
    static const int R[8] = { 13, 15, 26, 6, 17, 29, 16, 24 };
    for (int i = 0; i < 5; i++) {
        const int* r = &R[(i % 2) * 4];
        for (int j = 0; j < 4; j++) {
            x0 += x1;
            x1 = (x1 << r[j]) | (x1 >> (32 - r[j]));
            x1 ^= x0;
        }
        x0 += ks[(i + 1) % 3];
        x1 += ks[(i + 2) % 3] + (uint32_t)(i + 1);
    }
    o0 = x0; o1 = x1;
}

static void compute_init_idx(InitIdx* ii) {
    int num_rounds = (int)std::ceil(3.0 * std::log((double)NA) /
                                    std::log(4294967295.0));  // = 1
    for (int s = 0; s < NS; s++) {
        uint32_t k0, k1;
        tf2x32(0u, 42u, 0u, (uint32_t)s, k0, k1);   // keys = split(key(42), 8)

        std::vector<int> vals(NA);
        for (int i = 0; i < NA; i++) vals[i] = i;
        std::vector<std::pair<uint32_t, int>> p(NA);

        for (int r = 0; r < num_rounds; r++) {
            uint32_t nk0, nk1, sk0, sk1;
            tf2x32(k0, k1, 0u, 0u, nk0, nk1);  // new key
            tf2x32(k0, k1, 0u, 1u, sk0, sk1);  // subkey
            k0 = nk0; k1 = nk1;
            for (int i = 0; i < NA; i++) {
                uint32_t o0, o1;
                tf2x32(sk0, sk1, 0u, (uint32_t)i, o0, o1);
                p[i] = { o0 ^ o1, vals[i] };
            }
            std::stable_sort(p.begin(), p.end(),
                [](const std::pair<uint32_t, int>& x, const std::pair<uint32_t, int>& y) {
                    return x.first < y.first;
                });
            for (int i = 0; i < NA; i++) vals[i] = p[i].second;
        }
        for (int c = 0; c < NK; c++) ii->v[s * NK + c] = vals[c];
    }
}

extern "C" void kernel_launch(void* const* d_in, const int* in_sizes, int n_in,
                              void* d_out, int out_size) {
    (void)in_sizes; (void)n_in; (void)out_size;
    const float* cov = (const float*)d_in[0];
    float* out = (float*)d_out;

    InitIdx ii;
    compute_init_idx(&ii);

    k_prep<<<NS, NA>>>(cov);
    k_corr<<<NS * NA, 256>>>(cov);
    k_initc<<<NS, NA>>>(ii);

    for (int it = 0; it < NIT; it++) {
        k_assign_upd<<<dim3(NCH, NS), 512>>>();
        k_finishB<<<dim3(NK, NS), NA>>>(it);
    }

    k_lists<<<NS, 32>>>();
    k_gather<<<dim3(16, NK, NS), 256>>>(cov);
    k_cg<<<dim3(NK, NS), 1024>>>();
    k_Y<<<NS * NA, 256>>>(cov);
    k_inter<<<NS, NA>>>();
    k_winter<<<NS, 32>>>();
    k_final<<<NS, NA>>>(out);
}